// round 3
// baseline (speedup 1.0000x reference)
#include <cuda_runtime.h>

#define SIG_LEN  16777216
#define HOP      256
#define PAD      768
#define N_FRAMES 65539
#define N_ROWS   65542
#define HALF     513

// ---------------- compile-time tables (correctly-rounded, double precision) ----------------
constexpr double PI_D = 3.141592653589793238462643383279502884;

constexpr double tcos(double x) {            // |x| <= pi/4
    double x2 = x * x, term = 1.0, s = 1.0;
    for (int i = 1; i <= 10; i++) { term *= -x2 / ((2.0 * i - 1.0) * (2.0 * i)); s += term; }
    return s;
}
constexpr double tsin(double x) {
    double x2 = x * x, term = x, s = x;
    for (int i = 1; i <= 10; i++) { term *= -x2 / ((2.0 * i) * (2.0 * i + 1.0)); s += term; }
    return s;
}
constexpr double cpi(double t) {             // cos(pi*t)
    while (t >= 2.0) t -= 2.0;
    while (t < 0.0) t += 2.0;
    if (t > 1.0) t = 2.0 - t;
    double sg = 1.0;
    if (t > 0.5) { t = 1.0 - t; sg = -1.0; }
    return sg * (t <= 0.25 ? tcos(PI_D * t) : tsin(PI_D * (0.5 - t)));
}
constexpr double spi(double t) {             // sin(pi*t)
    while (t >= 2.0) t -= 2.0;
    while (t < 0.0) t += 2.0;
    double sg = 1.0;
    if (t > 1.0) { t -= 1.0; sg = -1.0; }
    if (t > 0.5) t = 1.0 - t;
    return sg * (t <= 0.25 ? tsin(PI_D * t) : tcos(PI_D * (0.5 - t)));
}

struct Tables {
    float2 tw512[512];    // e^{-2pi i k/512}
    float2 tw64[64];      // [j2*8+n0] = e^{-2pi i n0 j2/64}
    float2 tw1024[513];   // e^{-i pi k/512}
    float2 win[512];      // (w[2n], w[2n+1]) / 32
};
constexpr Tables mk_tables() {
    Tables T{};
    for (int k = 0; k < 512; k++)
        T.tw512[k] = float2{ (float)cpi(k / 256.0), (float)(-spi(k / 256.0)) };
    for (int j2 = 0; j2 < 8; j2++)
        for (int n0 = 0; n0 < 8; n0++)
            T.tw64[j2 * 8 + n0] = float2{ (float)cpi(n0 * j2 / 32.0),
                                          (float)(-spi(n0 * j2 / 32.0)) };
    for (int k = 0; k <= 512; k++)
        T.tw1024[k] = float2{ (float)cpi(k / 512.0), (float)(-spi(k / 512.0)) };
    for (int n = 0; n < 512; n++)
        T.win[n] = float2{ (float)((0.54 - 0.46 * cpi(2.0 * (2 * n) / 1023.0)) / 32.0),
                           (float)((0.54 - 0.46 * cpi(2.0 * (2 * n + 1) / 1023.0)) / 32.0) };
    return T;
}
__device__ constexpr Tables TAB = mk_tables();

// ---------------- complex helpers ----------------
__device__ __forceinline__ float2 cadd(float2 a, float2 b) { return make_float2(a.x + b.x, a.y + b.y); }
__device__ __forceinline__ float2 csub(float2 a, float2 b) { return make_float2(a.x - b.x, a.y - b.y); }
__device__ __forceinline__ float2 cmul(float2 a, float2 b) {
    return make_float2(a.x * b.x - a.y * b.y, a.x * b.y + a.y * b.x);
}
__device__ __forceinline__ float2 cmi(float2 a) { return make_float2(a.y, -a.x); }   // * -i

// 8-point DFT, natural order in/out: o[j] = sum_m a[m] e^{-2pi i mj/8}
__device__ __forceinline__ void fft8(float2* a) {
    const float C = 0.70710678118654752440f;
    float2 s0 = cadd(a[0], a[4]), s1 = csub(a[0], a[4]);
    float2 s2 = cadd(a[2], a[6]), s3 = csub(a[2], a[6]);
    float2 t0 = cadd(a[1], a[5]), t1 = csub(a[1], a[5]);
    float2 t2 = cadd(a[3], a[7]), t3 = csub(a[3], a[7]);
    float2 E0 = cadd(s0, s2), E2 = csub(s0, s2);
    float2 E1 = cadd(s1, cmi(s3)), E3 = csub(s1, cmi(s3));
    float2 O0 = cadd(t0, t2), O2 = csub(t0, t2);
    float2 O1 = cadd(t1, cmi(t3)), O3 = csub(t1, cmi(t3));
    float2 W1 = make_float2(C * (O1.x + O1.y), C * (O1.y - O1.x));   // O1 * w8^1
    float2 W2 = cmi(O2);                                             // O2 * w8^2
    float2 W3 = make_float2(C * (O3.y - O3.x), -C * (O3.x + O3.y));  // O3 * w8^3
    a[0] = cadd(E0, O0); a[4] = csub(E0, O0);
    a[1] = cadd(E1, W1); a[5] = csub(E1, W1);
    a[2] = cadd(E2, W2); a[6] = csub(E2, W2);
    a[3] = cadd(E3, W3); a[7] = csub(E3, W3);
}

// ---------------- single fused STFT kernel ----------------
// 4 consecutive frames per 256-thread block; 64 threads/frame, 8 complex pts/thread.
// 512-pt complex FFT of even/odd-packed reals via 8x8x8 DIF, then rfft untangle.
__global__ __launch_bounds__(256) void stft_kernel(const float* __restrict__ x,
                                                   float* __restrict__ out) {
    __shared__ float2 sA[4][512];
    __shared__ float2 sB[4][512];

    const int t  = threadIdx.x;
    const int fr = t >> 6;            // frame slot within block
    const int tl = t & 63;            // thread within frame
    const int f  = blockIdx.x * 4 + fr;
    const int start = f * HOP - PAD;
    const int hi = tl >> 3, lo = tl & 7;

    float2 v[8];

    // ---- load + window: c[n] = (x[2n]*w[2n], x[2n+1]*w[2n+1]), n = tl + 64m ----
    const bool inb = (start >= 0) && (start + 1024 <= SIG_LEN);
    #pragma unroll
    for (int m = 0; m < 8; m++) {
        int n = tl + 64 * m;
        float2 w = TAB.win[n];
        float a, b;
        if (inb) {
            float2 xv = *(const float2*)(x + start + 2 * n);
            a = xv.x; b = xv.y;
        } else {
            int i0 = start + 2 * n;
            a = (i0     >= 0 && i0     < SIG_LEN) ? x[i0]     : 0.0f;
            b = (i0 + 1 >= 0 && i0 + 1 < SIG_LEN) ? x[i0 + 1] : 0.0f;
        }
        v[m] = make_float2(a * w.x, b * w.y);
    }

    // ---- stage 1: u_j[tl] = FFT8_m(c[tl+64m])[j] * tw512[tl*j] ----
    fft8(v);
    #pragma unroll
    for (int j = 1; j < 8; j++) v[j] = cmul(v[j], TAB.tw512[tl * j]);
    float2* bufA = sA[fr];
    #pragma unroll
    for (int j = 0; j < 8; j++)
        bufA[j * 64 + (((hi ^ j) & 7) << 3) + lo] = v[j];     // addr1(j, n1=hi, n0=lo)
    __syncthreads();

    // ---- stage 2: thread (j=hi, n0=lo): v_{j2}[lo] = FFT8_m(u_hi[lo+8m])[j2] * tw64[j2][lo] ----
    #pragma unroll
    for (int m = 0; m < 8; m++)
        v[m] = bufA[hi * 64 + (((m ^ hi) & 7) << 3) + lo];    // addr1(hi, m, lo)
    fft8(v);
    #pragma unroll
    for (int j2 = 1; j2 < 8; j2++) v[j2] = cmul(v[j2], TAB.tw64[j2 * 8 + lo]);
    float2* bufB = sB[fr];
    #pragma unroll
    for (int j2 = 0; j2 < 8; j2++)
        bufB[j2 * 64 + hi * 8 + (lo ^ j2)] = v[j2];           // addr2(j=hi, j2, n0=lo)
    __syncthreads();

    // ---- stage 3: thread (j=hi, j2=lo): X[hi + 8*lo + 64*j3] = FFT8_n0(v)[j3] ----
    #pragma unroll
    for (int n0 = 0; n0 < 8; n0++)
        v[n0] = bufB[lo * 64 + hi * 8 + (n0 ^ lo)];           // addr2(hi, lo, n0)
    fft8(v);
    #pragma unroll
    for (int j3 = 0; j3 < 8; j3++) {
        int k = hi + 8 * lo + 64 * j3;
        bufA[k ^ lo] = v[j3];                                 // addrR(k) = k ^ ((k>>3)&7)
    }
    __syncthreads();

    // ---- untangle rfft + (-1)^k circular-shift + mag/phase ----
    if (f < N_ROWS) {
        float* om = out + (size_t)f * HALF;
        float* op = out + (size_t)N_ROWS * HALF + (size_t)f * HALF;
        if (f >= N_FRAMES) {
            #pragma unroll
            for (int q = 0; q < 8; q++) { int k = tl + 64 * q; om[k] = 0.0f; op[k] = 0.0f; }
            if (tl == 0) { om[512] = 0.0f; op[512] = 0.0f; }
        } else {
            #pragma unroll
            for (int q = 0; q < 9; q++) {
                int k;
                if (q == 8) { if (tl != 0) break; k = 512; } else k = tl + 64 * q;
                int ka = k & 511, kb = (512 - k) & 511;
                float2 Zk = bufA[ka ^ ((ka >> 3) & 7)];
                float2 Zm = bufA[kb ^ ((kb >> 3) & 7)];
                float Ar = 0.5f * (Zk.x + Zm.x), Ai = 0.5f * (Zk.y - Zm.y);
                float Br = 0.5f * (Zk.x - Zm.x), Bi = 0.5f * (Zk.y + Zm.y);
                float2 W = TAB.tw1024[k];
                float wbr = W.x * Br - W.y * Bi;
                float wbi = W.x * Bi + W.y * Br;
                float Xr = Ar + wbi;
                float Xi = Ai - wbr;
                if (k & 1) { Xr = -Xr; Xi = -Xi; }
                om[k] = sqrtf(Xr * Xr + Xi * Xi);
                op[k] = atan2f(Xi, Xr);
            }
        }
    }
}

extern "C" void kernel_launch(void* const* d_in, const int* in_sizes, int n_in,
                              void* d_out, int out_size) {
    const float* x = (const float*)d_in[0];
    float* out = (float*)d_out;
    stft_kernel<<<(N_ROWS + 3) / 4, 256>>>(x, out);
}

// round 5
// speedup vs baseline: 1.9228x; 1.9228x over previous
#include <cuda_runtime.h>

#define SIG_LEN  16777216
#define HOP      256
#define PAD      768
#define N_FRAMES 65539
#define N_ROWS   65542
#define HALF     513

// ---------------- compile-time tables (correctly-rounded, double precision) ----------------
constexpr double PI_D = 3.141592653589793238462643383279502884;

constexpr double tcos(double x) {            // |x| <= pi/4
    double x2 = x * x, term = 1.0, s = 1.0;
    for (int i = 1; i <= 10; i++) { term *= -x2 / ((2.0 * i - 1.0) * (2.0 * i)); s += term; }
    return s;
}
constexpr double tsin(double x) {
    double x2 = x * x, term = x, s = x;
    for (int i = 1; i <= 10; i++) { term *= -x2 / ((2.0 * i) * (2.0 * i + 1.0)); s += term; }
    return s;
}
constexpr double cpi(double t) {             // cos(pi*t)
    while (t >= 2.0) t -= 2.0;
    while (t < 0.0) t += 2.0;
    if (t > 1.0) t = 2.0 - t;
    double sg = 1.0;
    if (t > 0.5) { t = 1.0 - t; sg = -1.0; }
    return sg * (t <= 0.25 ? tcos(PI_D * t) : tsin(PI_D * (0.5 - t)));
}
constexpr double spi(double t) {             // sin(pi*t)
    while (t >= 2.0) t -= 2.0;
    while (t < 0.0) t += 2.0;
    double sg = 1.0;
    if (t > 1.0) { t -= 1.0; sg = -1.0; }
    if (t > 0.5) t = 1.0 - t;
    return sg * (t <= 0.25 ? tsin(PI_D * t) : tcos(PI_D * (0.5 - t)));
}

struct Tables {
    float2 tw512[512];    // e^{-2pi i k/512}
    float2 tw64[64];      // [j2*8+n0] = e^{-2pi i n0 j2/64}
    float2 tw1024[513];   // e^{-i pi k/512}
    float2 win[512];      // (w[2n], w[2n+1]) / 32
};
constexpr Tables mk_tables() {
    Tables T{};
    for (int k = 0; k < 512; k++)
        T.tw512[k] = float2{ (float)cpi(k / 256.0), (float)(-spi(k / 256.0)) };
    for (int j2 = 0; j2 < 8; j2++)
        for (int n0 = 0; n0 < 8; n0++)
            T.tw64[j2 * 8 + n0] = float2{ (float)cpi(n0 * j2 / 32.0),
                                          (float)(-spi(n0 * j2 / 32.0)) };
    for (int k = 0; k <= 512; k++)
        T.tw1024[k] = float2{ (float)cpi(k / 512.0), (float)(-spi(k / 512.0)) };
    for (int n = 0; n < 512; n++)
        T.win[n] = float2{ (float)((0.54 - 0.46 * cpi(2.0 * (2 * n) / 1023.0)) / 32.0),
                           (float)((0.54 - 0.46 * cpi(2.0 * (2 * n + 1) / 1023.0)) / 32.0) };
    return T;
}
__device__ constexpr Tables TAB = mk_tables();

// ---------------- helpers ----------------
__device__ __forceinline__ float2 cadd(float2 a, float2 b) { return make_float2(a.x + b.x, a.y + b.y); }
__device__ __forceinline__ float2 csub(float2 a, float2 b) { return make_float2(a.x - b.x, a.y - b.y); }
__device__ __forceinline__ float2 cmul(float2 a, float2 b) {
    return make_float2(a.x * b.x - a.y * b.y, a.x * b.y + a.y * b.x);
}
__device__ __forceinline__ float2 cmi(float2 a) { return make_float2(a.y, -a.x); }   // * -i

__device__ __forceinline__ float fsqrt_fast(float x) {
    float r; asm("sqrt.approx.f32 %0, %1;" : "=f"(r) : "f"(x)); return r;
}

// atan2, cephes-style octant reduction, abs err ~2e-7 rad.
// Sign of result from (y < 0) comparison, NOT copysign: maps y == -0.0 to +pi,
// matching the reference (rfft bins 0/512 have structurally +0 imag; our pair
// formula produces -0.0 at the Nyquist bin).
__device__ __forceinline__ float fatan2_fast(float y, float x) {
    const float PI    = 3.14159265358979323f;
    const float PI_2  = 1.57079632679489662f;
    const float PI_4  = 0.78539816339744831f;
    float ax = fabsf(x), ay = fabsf(y);
    float mn = fminf(ax, ay), mx = fmaxf(ax, ay);
    bool big = mn > 0.41421356f * mx;              // reduce to |t| <= tan(pi/8)
    float num = big ? (mn - mx) : mn;
    float den = big ? (mn + mx) : mx;
    float t = __fdividef(num, den);
    t = (den == 0.0f) ? 0.0f : t;                  // atan2(0,0) = 0
    float s = t * t;
    float p = fmaf(fmaf(fmaf(8.05374449538e-2f, s, -1.38776856032e-1f), s,
                        1.99777106478e-1f), s, -3.33329491539e-1f);
    float r = fmaf(p * s, t, t);                   // atan(t)
    if (big) r += PI_4;
    if (ay > ax) r = PI_2 - r;
    if (x < 0.0f) r = PI - r;
    return (y < 0.0f) ? -r : r;
}

// 8-point DFT, natural order in/out
__device__ __forceinline__ void fft8(float2* a) {
    const float C = 0.70710678118654752440f;
    float2 s0 = cadd(a[0], a[4]), s1 = csub(a[0], a[4]);
    float2 s2 = cadd(a[2], a[6]), s3 = csub(a[2], a[6]);
    float2 t0 = cadd(a[1], a[5]), t1 = csub(a[1], a[5]);
    float2 t2 = cadd(a[3], a[7]), t3 = csub(a[3], a[7]);
    float2 E0 = cadd(s0, s2), E2 = csub(s0, s2);
    float2 E1 = cadd(s1, cmi(s3)), E3 = csub(s1, cmi(s3));
    float2 O0 = cadd(t0, t2), O2 = csub(t0, t2);
    float2 O1 = cadd(t1, cmi(t3)), O3 = csub(t1, cmi(t3));
    float2 W1 = make_float2(C * (O1.x + O1.y), C * (O1.y - O1.x));
    float2 W2 = cmi(O2);
    float2 W3 = make_float2(C * (O3.y - O3.x), -C * (O3.x + O3.y));
    a[0] = cadd(E0, O0); a[4] = csub(E0, O0);
    a[1] = cadd(E1, W1); a[5] = csub(E1, W1);
    a[2] = cadd(E2, W2); a[6] = csub(E2, W2);
    a[3] = cadd(E3, W3); a[7] = csub(E3, W3);
}

// ---------------- single fused STFT kernel ----------------
// 4 consecutive frames per 256-thread block; 64 threads/frame, 8 complex pts/thread.
__global__ __launch_bounds__(256) void stft_kernel(const float* __restrict__ x,
                                                   float* __restrict__ out) {
    __shared__ float2 sA[4][512];
    __shared__ float2 sB[4][512];

    const int t  = threadIdx.x;
    const int fr = t >> 6;
    const int tl = t & 63;
    const int f  = blockIdx.x * 4 + fr;
    const int start = f * HOP - PAD;
    const int hi = tl >> 3, lo = tl & 7;

    float2 v[8];

    // ---- load + window ----
    const bool inb = (start >= 0) && (start + 1024 <= SIG_LEN);
    #pragma unroll
    for (int m = 0; m < 8; m++) {
        int n = tl + 64 * m;
        float2 w = TAB.win[n];
        float a, b;
        if (inb) {
            float2 xv = *(const float2*)(x + start + 2 * n);
            a = xv.x; b = xv.y;
        } else {
            int i0 = start + 2 * n;
            a = (i0     >= 0 && i0     < SIG_LEN) ? x[i0]     : 0.0f;
            b = (i0 + 1 >= 0 && i0 + 1 < SIG_LEN) ? x[i0 + 1] : 0.0f;
        }
        v[m] = make_float2(a * w.x, b * w.y);
    }

    // ---- stage 1 ----
    fft8(v);
    #pragma unroll
    for (int j = 1; j < 8; j++) v[j] = cmul(v[j], TAB.tw512[tl * j]);
    float2* bufA = sA[fr];
    #pragma unroll
    for (int j = 0; j < 8; j++)
        bufA[j * 64 + (((hi ^ j) & 7) << 3) + lo] = v[j];
    __syncthreads();

    // ---- stage 2 ----
    #pragma unroll
    for (int m = 0; m < 8; m++)
        v[m] = bufA[hi * 64 + (((m ^ hi) & 7) << 3) + lo];
    fft8(v);
    #pragma unroll
    for (int j2 = 1; j2 < 8; j2++) v[j2] = cmul(v[j2], TAB.tw64[j2 * 8 + lo]);
    float2* bufB = sB[fr];
    #pragma unroll
    for (int j2 = 0; j2 < 8; j2++)
        bufB[j2 * 64 + hi * 8 + (lo ^ j2)] = v[j2];
    __syncthreads();

    // ---- stage 3 ----
    #pragma unroll
    for (int n0 = 0; n0 < 8; n0++)
        v[n0] = bufB[lo * 64 + hi * 8 + (n0 ^ lo)];
    fft8(v);
    #pragma unroll
    for (int j3 = 0; j3 < 8; j3++) {
        int k = hi + 8 * lo + 64 * j3;
        bufA[k ^ lo] = v[j3];               // addrR(k) = k ^ ((k>>3)&7)
    }
    __syncthreads();

    // ---- conjugate-pair untangle + (-1)^k shift + mag/phase ----
    if (f < N_ROWS) {
        float* om = out + (size_t)f * HALF;
        float* op = out + (size_t)N_ROWS * HALF + (size_t)f * HALF;
        if (f >= N_FRAMES) {
            #pragma unroll
            for (int q = 0; q < 8; q++) { int k = tl + 64 * q; om[k] = 0.0f; op[k] = 0.0f; }
            if (tl == 0) { om[512] = 0.0f; op[512] = 0.0f; }
        } else {
            const float sg = (tl & 1) ? -1.0f : 1.0f;   // (-1)^k, same for k and 512-k
            #pragma unroll
            for (int q = 0; q < 4; q++) {
                int k  = tl + 64 * q;                   // 0..255
                int ka = k & 511, kb = (512 - k) & 511;
                float2 Zk = bufA[ka ^ ((ka >> 3) & 7)];
                float2 Zm = bufA[kb ^ ((kb >> 3) & 7)];
                float Ar = 0.5f * (Zk.x + Zm.x), Ai = 0.5f * (Zk.y - Zm.y);
                float Br = 0.5f * (Zk.x - Zm.x), Bi = 0.5f * (Zk.y + Zm.y);
                float2 W = TAB.tw1024[k];
                float wbr = W.x * Br - W.y * Bi;
                float wbi = W.x * Bi + W.y * Br;
                float Xkr = Ar + wbi, Xki = Ai - wbr;      // X[k]
                float Xmr = Ar - wbi, Xmi = -Ai - wbr;     // X[512-k]
                om[k] = fsqrt_fast(Xkr * Xkr + Xki * Xki);
                op[k] = fatan2_fast(sg * Xki, sg * Xkr);
                int m = 512 - k;
                om[m] = fsqrt_fast(Xmr * Xmr + Xmi * Xmi);
                op[m] = fatan2_fast(sg * Xmi, sg * Xmr);
            }
            if (tl == 0) {                              // center bin k=256, even parity
                float2 Z = bufA[256 ^ ((256 >> 3) & 7)];
                // X[256] = conj(Z256)
                om[256] = fsqrt_fast(Z.x * Z.x + Z.y * Z.y);
                op[256] = fatan2_fast(-Z.y, Z.x);
            }
        }
    }
}

extern "C" void kernel_launch(void* const* d_in, const int* in_sizes, int n_in,
                              void* d_out, int out_size) {
    const float* x = (const float*)d_in[0];
    float* out = (float*)d_out;
    stft_kernel<<<(N_ROWS + 3) / 4, 256>>>(x, out);
}

// round 6
// speedup vs baseline: 1.9420x; 1.0100x over previous
#include <cuda_runtime.h>

#define SIG_LEN  16777216
#define HOP      256
#define PAD      768
#define N_FRAMES 65539
#define N_ROWS   65542
#define HALF     513

// ---------------- compile-time tables (correctly-rounded, double precision) ----------------
constexpr double PI_D = 3.141592653589793238462643383279502884;

constexpr double tcos(double x) {            // |x| <= pi/4
    double x2 = x * x, term = 1.0, s = 1.0;
    for (int i = 1; i <= 10; i++) { term *= -x2 / ((2.0 * i - 1.0) * (2.0 * i)); s += term; }
    return s;
}
constexpr double tsin(double x) {
    double x2 = x * x, term = x, s = x;
    for (int i = 1; i <= 10; i++) { term *= -x2 / ((2.0 * i) * (2.0 * i + 1.0)); s += term; }
    return s;
}
constexpr double cpi(double t) {             // cos(pi*t)
    while (t >= 2.0) t -= 2.0;
    while (t < 0.0) t += 2.0;
    if (t > 1.0) t = 2.0 - t;
    double sg = 1.0;
    if (t > 0.5) { t = 1.0 - t; sg = -1.0; }
    return sg * (t <= 0.25 ? tcos(PI_D * t) : tsin(PI_D * (0.5 - t)));
}
constexpr double spi(double t) {             // sin(pi*t)
    while (t >= 2.0) t -= 2.0;
    while (t < 0.0) t += 2.0;
    double sg = 1.0;
    if (t > 1.0) { t -= 1.0; sg = -1.0; }
    if (t > 0.5) t = 1.0 - t;
    return sg * (t <= 0.25 ? tsin(PI_D * t) : tcos(PI_D * (0.5 - t)));
}

struct Tables {
    float2 tw512[512];    // e^{-2pi i k/512}
    float2 tw64[64];      // [j2*8+n0] = e^{-2pi i n0 j2/64}
    float2 tw1024[513];   // e^{-i pi k/512}
    float2 win[512];      // (w[2n], w[2n+1]) / 32
};
constexpr Tables mk_tables() {
    Tables T{};
    for (int k = 0; k < 512; k++)
        T.tw512[k] = float2{ (float)cpi(k / 256.0), (float)(-spi(k / 256.0)) };
    for (int j2 = 0; j2 < 8; j2++)
        for (int n0 = 0; n0 < 8; n0++)
            T.tw64[j2 * 8 + n0] = float2{ (float)cpi(n0 * j2 / 32.0),
                                          (float)(-spi(n0 * j2 / 32.0)) };
    for (int k = 0; k <= 512; k++)
        T.tw1024[k] = float2{ (float)cpi(k / 512.0), (float)(-spi(k / 512.0)) };
    for (int n = 0; n < 512; n++)
        T.win[n] = float2{ (float)((0.54 - 0.46 * cpi(2.0 * (2 * n) / 1023.0)) / 32.0),
                           (float)((0.54 - 0.46 * cpi(2.0 * (2 * n + 1) / 1023.0)) / 32.0) };
    return T;
}
__device__ constexpr Tables TAB = mk_tables();

// ---------------- helpers ----------------
__device__ __forceinline__ float2 cadd(float2 a, float2 b) { return make_float2(a.x + b.x, a.y + b.y); }
__device__ __forceinline__ float2 csub(float2 a, float2 b) { return make_float2(a.x - b.x, a.y - b.y); }
__device__ __forceinline__ float2 cmul(float2 a, float2 b) {
    return make_float2(a.x * b.x - a.y * b.y, a.x * b.y + a.y * b.x);
}
__device__ __forceinline__ float2 cmi(float2 a) { return make_float2(a.y, -a.x); }   // * -i

__device__ __forceinline__ float fsqrt_fast(float x) {
    float r; asm("sqrt.approx.f32 %0, %1;" : "=f"(r) : "f"(x)); return r;
}

// atan2, cephes-style octant reduction, abs err ~2e-7 rad.
// Sign of result from (y < 0) comparison, NOT copysign: maps y == -0.0 to +pi,
// matching the reference (rfft bins 0/512 have structurally +0 imag; our pair
// formula produces -0.0 at the Nyquist bin).
__device__ __forceinline__ float fatan2_fast(float y, float x) {
    const float PI    = 3.14159265358979323f;
    const float PI_2  = 1.57079632679489662f;
    const float PI_4  = 0.78539816339744831f;
    float ax = fabsf(x), ay = fabsf(y);
    float mn = fminf(ax, ay), mx = fmaxf(ax, ay);
    bool big = mn > 0.41421356f * mx;              // reduce to |t| <= tan(pi/8)
    float num = big ? (mn - mx) : mn;
    float den = big ? (mn + mx) : mx;
    float t = __fdividef(num, den);
    t = (den == 0.0f) ? 0.0f : t;                  // atan2(0,0) = 0
    float s = t * t;
    float p = fmaf(fmaf(fmaf(8.05374449538e-2f, s, -1.38776856032e-1f), s,
                        1.99777106478e-1f), s, -3.33329491539e-1f);
    float r = fmaf(p * s, t, t);                   // atan(t)
    if (big) r += PI_4;
    if (ay > ax) r = PI_2 - r;
    if (x < 0.0f) r = PI - r;
    return (y < 0.0f) ? -r : r;
}

// 8-point DFT, natural order in/out
__device__ __forceinline__ void fft8(float2* a) {
    const float C = 0.70710678118654752440f;
    float2 s0 = cadd(a[0], a[4]), s1 = csub(a[0], a[4]);
    float2 s2 = cadd(a[2], a[6]), s3 = csub(a[2], a[6]);
    float2 t0 = cadd(a[1], a[5]), t1 = csub(a[1], a[5]);
    float2 t2 = cadd(a[3], a[7]), t3 = csub(a[3], a[7]);
    float2 E0 = cadd(s0, s2), E2 = csub(s0, s2);
    float2 E1 = cadd(s1, cmi(s3)), E3 = csub(s1, cmi(s3));
    float2 O0 = cadd(t0, t2), O2 = csub(t0, t2);
    float2 O1 = cadd(t1, cmi(t3)), O3 = csub(t1, cmi(t3));
    float2 W1 = make_float2(C * (O1.x + O1.y), C * (O1.y - O1.x));
    float2 W2 = cmi(O2);
    float2 W3 = make_float2(C * (O3.y - O3.x), -C * (O3.x + O3.y));
    a[0] = cadd(E0, O0); a[4] = csub(E0, O0);
    a[1] = cadd(E1, W1); a[5] = csub(E1, W1);
    a[2] = cadd(E2, W2); a[6] = csub(E2, W2);
    a[3] = cadd(E3, W3); a[7] = csub(E3, W3);
}

// ---------------- single fused STFT kernel ----------------
// 4 consecutive frames per 256-thread block; 64 threads/frame, 8 complex pts/thread.
__global__ __launch_bounds__(256) void stft_kernel(const float* __restrict__ x,
                                                   float* __restrict__ out) {
    __shared__ float2 sA[4][512];
    __shared__ float2 sB[4][512];

    const int t  = threadIdx.x;
    const int fr = t >> 6;
    const int tl = t & 63;
    const int f  = blockIdx.x * 4 + fr;
    const int start = f * HOP - PAD;
    const int hi = tl >> 3, lo = tl & 7;

    float2 v[8];

    // ---- load + window ----
    const bool inb = (start >= 0) && (start + 1024 <= SIG_LEN);
    #pragma unroll
    for (int m = 0; m < 8; m++) {
        int n = tl + 64 * m;
        float2 w = TAB.win[n];
        float a, b;
        if (inb) {
            float2 xv = *(const float2*)(x + start + 2 * n);
            a = xv.x; b = xv.y;
        } else {
            int i0 = start + 2 * n;
            a = (i0     >= 0 && i0     < SIG_LEN) ? x[i0]     : 0.0f;
            b = (i0 + 1 >= 0 && i0 + 1 < SIG_LEN) ? x[i0 + 1] : 0.0f;
        }
        v[m] = make_float2(a * w.x, b * w.y);
    }

    // ---- stage 1: twiddles w^j computed from one table load (kills 54 L1
    //      wavefronts/warp of strided tw512[tl*j] loads; shallow power tree) ----
    fft8(v);
    {
        float2 w1 = TAB.tw512[tl];
        float2 w2 = cmul(w1, w1);
        float2 w3 = cmul(w2, w1);
        float2 w4 = cmul(w2, w2);
        float2 w5 = cmul(w4, w1);
        float2 w6 = cmul(w3, w3);
        float2 w7 = cmul(w4, w3);
        v[1] = cmul(v[1], w1);
        v[2] = cmul(v[2], w2);
        v[3] = cmul(v[3], w3);
        v[4] = cmul(v[4], w4);
        v[5] = cmul(v[5], w5);
        v[6] = cmul(v[6], w6);
        v[7] = cmul(v[7], w7);
    }
    float2* bufA = sA[fr];
    #pragma unroll
    for (int j = 0; j < 8; j++)
        bufA[j * 64 + (((hi ^ j) & 7) << 3) + lo] = v[j];
    __syncthreads();

    // ---- stage 2 ----
    #pragma unroll
    for (int m = 0; m < 8; m++)
        v[m] = bufA[hi * 64 + (((m ^ hi) & 7) << 3) + lo];
    fft8(v);
    #pragma unroll
    for (int j2 = 1; j2 < 8; j2++) v[j2] = cmul(v[j2], TAB.tw64[j2 * 8 + lo]);
    float2* bufB = sB[fr];
    #pragma unroll
    for (int j2 = 0; j2 < 8; j2++)
        bufB[j2 * 64 + hi * 8 + (lo ^ j2)] = v[j2];
    __syncthreads();

    // ---- stage 3 ----
    #pragma unroll
    for (int n0 = 0; n0 < 8; n0++)
        v[n0] = bufB[lo * 64 + hi * 8 + (n0 ^ lo)];
    fft8(v);
    #pragma unroll
    for (int j3 = 0; j3 < 8; j3++) {
        int k = hi + 8 * lo + 64 * j3;
        bufA[k ^ lo] = v[j3];               // addrR(k) = k ^ ((k>>3)&7)
    }
    __syncthreads();

    // ---- conjugate-pair untangle + (-1)^k shift + mag/phase ----
    if (f < N_ROWS) {
        float* om = out + (size_t)f * HALF;
        float* op = out + (size_t)N_ROWS * HALF + (size_t)f * HALF;
        if (f >= N_FRAMES) {
            #pragma unroll
            for (int q = 0; q < 8; q++) { int k = tl + 64 * q; om[k] = 0.0f; op[k] = 0.0f; }
            if (tl == 0) { om[512] = 0.0f; op[512] = 0.0f; }
        } else {
            const float sg = (tl & 1) ? -1.0f : 1.0f;   // (-1)^k, same for k and 512-k
            #pragma unroll
            for (int q = 0; q < 4; q++) {
                int k  = tl + 64 * q;                   // 0..255
                int ka = k & 511, kb = (512 - k) & 511;
                float2 Zk = bufA[ka ^ ((ka >> 3) & 7)];
                float2 Zm = bufA[kb ^ ((kb >> 3) & 7)];
                float Ar = 0.5f * (Zk.x + Zm.x), Ai = 0.5f * (Zk.y - Zm.y);
                float Br = 0.5f * (Zk.x - Zm.x), Bi = 0.5f * (Zk.y + Zm.y);
                float2 W = TAB.tw1024[k];
                float wbr = W.x * Br - W.y * Bi;
                float wbi = W.x * Bi + W.y * Br;
                float Xkr = Ar + wbi, Xki = Ai - wbr;      // X[k]
                float Xmr = Ar - wbi, Xmi = -Ai - wbr;     // X[512-k]
                om[k] = fsqrt_fast(Xkr * Xkr + Xki * Xki);
                op[k] = fatan2_fast(sg * Xki, sg * Xkr);
                int m = 512 - k;
                om[m] = fsqrt_fast(Xmr * Xmr + Xmi * Xmi);
                op[m] = fatan2_fast(sg * Xmi, sg * Xmr);
            }
            if (tl == 0) {                              // center bin k=256, even parity
                float2 Z = bufA[256 ^ ((256 >> 3) & 7)];
                // X[256] = conj(Z256)
                om[256] = fsqrt_fast(Z.x * Z.x + Z.y * Z.y);
                op[256] = fatan2_fast(-Z.y, Z.x);
            }
        }
    }
}

extern "C" void kernel_launch(void* const* d_in, const int* in_sizes, int n_in,
                              void* d_out, int out_size) {
    const float* x = (const float*)d_in[0];
    float* out = (float*)d_out;
    stft_kernel<<<(N_ROWS + 3) / 4, 256>>>(x, out);
}

// round 7
// speedup vs baseline: 1.9656x; 1.0121x over previous
#include <cuda_runtime.h>

#define SIG_LEN  16777216
#define HOP      256
#define PAD      768
#define N_FRAMES 65539
#define N_ROWS   65542
#define HALF     513

// ---------------- compile-time tables (correctly-rounded, double precision) ----------------
constexpr double PI_D = 3.141592653589793238462643383279502884;

constexpr double tcos(double x) {
    double x2 = x * x, term = 1.0, s = 1.0;
    for (int i = 1; i <= 10; i++) { term *= -x2 / ((2.0 * i - 1.0) * (2.0 * i)); s += term; }
    return s;
}
constexpr double tsin(double x) {
    double x2 = x * x, term = x, s = x;
    for (int i = 1; i <= 10; i++) { term *= -x2 / ((2.0 * i) * (2.0 * i + 1.0)); s += term; }
    return s;
}
constexpr double cpi(double t) {
    while (t >= 2.0) t -= 2.0;
    while (t < 0.0) t += 2.0;
    if (t > 1.0) t = 2.0 - t;
    double sg = 1.0;
    if (t > 0.5) { t = 1.0 - t; sg = -1.0; }
    return sg * (t <= 0.25 ? tcos(PI_D * t) : tsin(PI_D * (0.5 - t)));
}
constexpr double spi(double t) {
    while (t >= 2.0) t -= 2.0;
    while (t < 0.0) t += 2.0;
    double sg = 1.0;
    if (t > 1.0) { t -= 1.0; sg = -1.0; }
    if (t > 0.5) t = 1.0 - t;
    return sg * (t <= 0.25 ? tsin(PI_D * t) : tcos(PI_D * (0.5 - t)));
}

struct Tables {
    float2 tw512[512];     // e^{-2pi i k/512}
    float4 tw64d[64];      // {c,c,s,s} for e^{-2pi i n0 j2/64}
    float4 tw1024d[513];   // {c,c,s,s} for e^{-i pi k/512}
    float2 win[512];       // (w[2n], w[2n+1]) / 32
};
constexpr Tables mk_tables() {
    Tables T{};
    for (int k = 0; k < 512; k++)
        T.tw512[k] = float2{ (float)cpi(k / 256.0), (float)(-spi(k / 256.0)) };
    for (int j2 = 0; j2 < 8; j2++)
        for (int n0 = 0; n0 < 8; n0++) {
            float c = (float)cpi(n0 * j2 / 32.0), s = (float)(-spi(n0 * j2 / 32.0));
            T.tw64d[j2 * 8 + n0] = float4{ c, c, s, s };
        }
    for (int k = 0; k <= 512; k++) {
        float c = (float)cpi(k / 512.0), s = (float)(-spi(k / 512.0));
        T.tw1024d[k] = float4{ c, c, s, s };
    }
    for (int n = 0; n < 512; n++)
        T.win[n] = float2{ (float)((0.54 - 0.46 * cpi(2.0 * (2 * n) / 1023.0)) / 32.0),
                           (float)((0.54 - 0.46 * cpi(2.0 * (2 * n + 1) / 1023.0)) / 32.0) };
    return T;
}
__device__ constexpr Tables TAB = mk_tables();

// ---------------- f32x2 packed primitives (2 frames in the 2 lanes) ----------------
typedef unsigned long long u64;

__device__ __forceinline__ u64 pk(float lo, float hi) {
    u64 r; asm("mov.b64 %0, {%1, %2};" : "=l"(r) : "f"(lo), "f"(hi)); return r;
}
__device__ __forceinline__ void upk(float& lo, float& hi, u64 v) {
    asm("mov.b64 {%0, %1}, %2;" : "=f"(lo), "=f"(hi) : "l"(v));
}
__device__ __forceinline__ u64 vadd(u64 a, u64 b) {
    u64 r; asm("add.rn.f32x2 %0, %1, %2;" : "=l"(r) : "l"(a), "l"(b)); return r;
}
__device__ __forceinline__ u64 vmul(u64 a, u64 b) {
    u64 r; asm("mul.rn.f32x2 %0, %1, %2;" : "=l"(r) : "l"(a), "l"(b)); return r;
}
__device__ __forceinline__ u64 vfma(u64 a, u64 b, u64 c) {
    u64 r; asm("fma.rn.f32x2 %0, %1, %2, %3;" : "=l"(r) : "l"(a), "l"(b), "l"(c)); return r;
}
__device__ __forceinline__ u64 vneg1() { return pk(-1.0f, -1.0f); }
__device__ __forceinline__ u64 vsub(u64 a, u64 b) { return vfma(b, vneg1(), a); }  // exact a-b

struct cp { u64 re, im; };
__device__ __forceinline__ cp cadd(cp a, cp b)   { return { vadd(a.re, b.re), vadd(a.im, b.im) }; }
__device__ __forceinline__ cp csub(cp a, cp b)   { return { vsub(a.re, b.re), vsub(a.im, b.im) }; }
// a + (-i)b = (are+bim, aim-bre);  a - (-i)b = (are-bim, aim+bre)
__device__ __forceinline__ cp caddmi(cp a, cp b) { return { vadd(a.re, b.im), vsub(a.im, b.re) }; }
__device__ __forceinline__ cp csubmi(cp a, cp b) { return { vsub(a.re, b.im), vadd(a.im, b.re) }; }
__device__ __forceinline__ cp cpmul(cp a, cp b) {
    cp r;
    r.re = vsub(vmul(a.re, b.re), vmul(a.im, b.im));
    r.im = vfma(a.re, b.im, vmul(a.im, b.re));
    return r;
}

__device__ __forceinline__ float fsqrt_fast(float x) {
    float r; asm("sqrt.approx.f32 %0, %1;" : "=f"(r) : "f"(x)); return r;
}

// atan2, cephes-style, abs err ~2e-7 rad. (y<0) sign rule maps -0.0 -> +pi (Nyquist).
__device__ __forceinline__ float fatan2_fast(float y, float x) {
    const float PI   = 3.14159265358979323f;
    const float PI_2 = 1.57079632679489662f;
    const float PI_4 = 0.78539816339744831f;
    float ax = fabsf(x), ay = fabsf(y);
    float mn = fminf(ax, ay), mx = fmaxf(ax, ay);
    bool big = mn > 0.41421356f * mx;
    float num = big ? (mn - mx) : mn;
    float den = big ? (mn + mx) : mx;
    float t = __fdividef(num, den);
    t = (den == 0.0f) ? 0.0f : t;
    float s = t * t;
    float p = fmaf(fmaf(fmaf(8.05374449538e-2f, s, -1.38776856032e-1f), s,
                        1.99777106478e-1f), s, -3.33329491539e-1f);
    float r = fmaf(p * s, t, t);
    if (big) r += PI_4;
    if (ay > ax) r = PI_2 - r;
    if (x < 0.0f) r = PI - r;
    return (y < 0.0f) ? -r : r;
}

// packed 8-point DFT (both frames simultaneously)
__device__ __forceinline__ void fft8p(cp* a) {
    const float Cf = 0.70710678118654752440f;
    u64 Cd = pk(Cf, Cf), nCd = pk(-Cf, -Cf);
    cp s0 = cadd(a[0], a[4]), s1 = csub(a[0], a[4]);
    cp s2 = cadd(a[2], a[6]), s3 = csub(a[2], a[6]);
    cp t0 = cadd(a[1], a[5]), t1 = csub(a[1], a[5]);
    cp t2 = cadd(a[3], a[7]), t3 = csub(a[3], a[7]);
    cp E0 = cadd(s0, s2), E2 = csub(s0, s2);
    cp E1 = caddmi(s1, s3), E3 = csubmi(s1, s3);
    cp O0 = cadd(t0, t2), O2 = csub(t0, t2);
    cp O1 = caddmi(t1, t3), O3 = csubmi(t1, t3);
    cp W1 = { vmul(vadd(O1.re, O1.im), Cd), vmul(vsub(O1.im, O1.re), Cd) };
    cp W3 = { vmul(vsub(O3.im, O3.re), Cd), vmul(vadd(O3.re, O3.im), nCd) };
    a[0] = cadd(E0, O0);   a[4] = csub(E0, O0);
    a[1] = cadd(E1, W1);   a[5] = csub(E1, W1);
    a[2] = caddmi(E2, O2); a[6] = csubmi(E2, O2);   // W2 = -i*O2 folded
    a[3] = cadd(E3, W3);   a[7] = csub(E3, W3);
}

// ---------------- fused STFT kernel: 128 threads, 2 frame-pairs (4 frames)/block ----------
__global__ __launch_bounds__(128, 6) void stft_kernel(const float* __restrict__ x,
                                                      float* __restrict__ out) {
    __shared__ ulonglong2 sA[2][512];
    __shared__ ulonglong2 sB[2][512];

    const int t  = threadIdx.x;
    const int pr = t >> 6;            // frame-pair slot (0-1)
    const int tl = t & 63;
    const int f0 = blockIdx.x * 4 + pr * 2;   // lane .x frame
    const int f1 = f0 + 1;                    // lane .y frame
    const int st0 = f0 * HOP - PAD;
    const int st1 = st0 + HOP;
    const int hi = tl >> 3, lo = tl & 7;

    cp v[8];

    // ---- load + window (both frames) ----
    const bool inb0 = (st0 >= 0) && (st0 + 1024 <= SIG_LEN);
    const bool inb1 = (st1 >= 0) && (st1 + 1024 <= SIG_LEN);
    #pragma unroll
    for (int m = 0; m < 8; m++) {
        int n = tl + 64 * m;
        float2 w = TAB.win[n];
        float a0, b0, a1, b1;
        if (inb0) { float2 xv = *(const float2*)(x + st0 + 2 * n); a0 = xv.x; b0 = xv.y; }
        else {
            int i0 = st0 + 2 * n;
            a0 = (i0     >= 0 && i0     < SIG_LEN) ? x[i0]     : 0.0f;
            b0 = (i0 + 1 >= 0 && i0 + 1 < SIG_LEN) ? x[i0 + 1] : 0.0f;
        }
        if (inb1) { float2 xv = *(const float2*)(x + st1 + 2 * n); a1 = xv.x; b1 = xv.y; }
        else {
            int i1 = st1 + 2 * n;
            a1 = (i1     >= 0 && i1     < SIG_LEN) ? x[i1]     : 0.0f;
            b1 = (i1 + 1 >= 0 && i1 + 1 < SIG_LEN) ? x[i1 + 1] : 0.0f;
        }
        v[m].re = vmul(pk(a0, a1), pk(w.x, w.x));
        v[m].im = vmul(pk(b0, b1), pk(w.y, w.y));
    }

    // ---- stage 1: fft8 + twiddle powers of tw512[tl] (shallow tree) ----
    fft8p(v);
    {
        float2 w1s = TAB.tw512[tl];
        cp w1 = { pk(w1s.x, w1s.x), pk(w1s.y, w1s.y) };
        cp w2 = cpmul(w1, w1);
        cp w3 = cpmul(w2, w1);
        cp w4 = cpmul(w2, w2);
        cp w5 = cpmul(w4, w1);
        cp w6 = cpmul(w3, w3);
        cp w7 = cpmul(w4, w3);
        v[1] = cpmul(v[1], w1);
        v[2] = cpmul(v[2], w2);
        v[3] = cpmul(v[3], w3);
        v[4] = cpmul(v[4], w4);
        v[5] = cpmul(v[5], w5);
        v[6] = cpmul(v[6], w6);
        v[7] = cpmul(v[7], w7);
    }
    ulonglong2* bufA = sA[pr];
    #pragma unroll
    for (int j = 0; j < 8; j++)
        bufA[j * 64 + (((hi ^ j) & 7) << 3) + lo] = make_ulonglong2(v[j].re, v[j].im);
    __syncthreads();

    // ---- stage 2 ----
    #pragma unroll
    for (int m = 0; m < 8; m++) {
        ulonglong2 e = bufA[hi * 64 + (((m ^ hi) & 7) << 3) + lo];
        v[m].re = e.x; v[m].im = e.y;
    }
    fft8p(v);
    #pragma unroll
    for (int j2 = 1; j2 < 8; j2++) {
        float4 wd = TAB.tw64d[j2 * 8 + lo];
        cp w = { pk(wd.x, wd.y), pk(wd.z, wd.w) };
        v[j2] = cpmul(v[j2], w);
    }
    ulonglong2* bufB = sB[pr];
    #pragma unroll
    for (int j2 = 0; j2 < 8; j2++)
        bufB[j2 * 64 + hi * 8 + (lo ^ j2)] = make_ulonglong2(v[j2].re, v[j2].im);
    __syncthreads();

    // ---- stage 3 ----
    #pragma unroll
    for (int n0 = 0; n0 < 8; n0++) {
        ulonglong2 e = bufB[lo * 64 + hi * 8 + (n0 ^ lo)];
        v[n0].re = e.x; v[n0].im = e.y;
    }
    fft8p(v);
    #pragma unroll
    for (int j3 = 0; j3 < 8; j3++) {
        int k = hi + 8 * lo + 64 * j3;
        bufA[k ^ lo] = make_ulonglong2(v[j3].re, v[j3].im);   // addrR(k)=k^((k>>3)&7)
    }
    __syncthreads();

    // ---- conjugate-pair untangle (packed) + (-1)^k shift + mag/phase (scalar/frame) ----
    float* om0 = out + (size_t)f0 * HALF;
    float* op0 = out + (size_t)N_ROWS * HALF + (size_t)f0 * HALF;
    float* om1 = om0 + HALF;
    float* op1 = op0 + HALF;
    const bool w0 = (f0 < N_FRAMES);
    const bool w1 = (f1 < N_FRAMES);
    const u64 Hd = pk(0.5f, 0.5f);

    const float sg = (tl & 1) ? -1.0f : 1.0f;
    #pragma unroll
    for (int q = 0; q < 4; q++) {
        int k  = tl + 64 * q;                  // 0..255
        int ka = k & 511, kb = (512 - k) & 511;
        ulonglong2 ek = bufA[ka ^ ((ka >> 3) & 7)];
        ulonglong2 em = bufA[kb ^ ((kb >> 3) & 7)];
        cp zk = { ek.x, ek.y }, zm = { em.x, em.y };
        u64 Ar = vmul(vadd(zk.re, zm.re), Hd);
        u64 Ai = vmul(vsub(zk.im, zm.im), Hd);
        u64 Br = vmul(vsub(zk.re, zm.re), Hd);
        u64 Bi = vmul(vadd(zk.im, zm.im), Hd);
        float4 wd = TAB.tw1024d[k];
        u64 wc = pk(wd.x, wd.y), ws = pk(wd.z, wd.w);
        u64 wbr = vsub(vmul(wc, Br), vmul(ws, Bi));
        u64 wbi = vfma(wc, Bi, vmul(ws, Br));
        u64 Xkr = vadd(Ar, wbi), Xki = vsub(Ai, wbr);
        u64 Xmr = vsub(Ar, wbi), Xmi = vmul(vadd(Ai, wbr), vneg1());
        u64 Mk = vfma(Xki, Xki, vmul(Xkr, Xkr));
        u64 Mm = vfma(Xmi, Xmi, vmul(Xmr, Xmr));
        float mk0, mk1, mm0, mm1, kr0, kr1, ki0, ki1, mr0, mr1, mi0, mi1;
        upk(mk0, mk1, Mk); upk(mm0, mm1, Mm);
        upk(kr0, kr1, Xkr); upk(ki0, ki1, Xki);
        upk(mr0, mr1, Xmr); upk(mi0, mi1, Xmi);
        int m = 512 - k;
        if (w0) {
            om0[k] = fsqrt_fast(mk0); op0[k] = fatan2_fast(sg * ki0, sg * kr0);
            om0[m] = fsqrt_fast(mm0); op0[m] = fatan2_fast(sg * mi0, sg * mr0);
        }
        if (w1) {
            om1[k] = fsqrt_fast(mk1); op1[k] = fatan2_fast(sg * ki1, sg * kr1);
            om1[m] = fsqrt_fast(mm1); op1[m] = fatan2_fast(sg * mi1, sg * mr1);
        }
    }
    if (tl == 0) {                      // center bin k=256: X = conj(Z256), even parity
        ulonglong2 e = bufA[256];       // 256 ^ ((256>>3)&7) == 256
        float zr0, zr1, zi0, zi1;
        upk(zr0, zr1, e.x); upk(zi0, zi1, e.y);
        if (w0) { om0[256] = fsqrt_fast(zr0 * zr0 + zi0 * zi0); op0[256] = fatan2_fast(-zi0, zr0); }
        if (w1) { om1[256] = fsqrt_fast(zr1 * zr1 + zi1 * zi1); op1[256] = fatan2_fast(-zi1, zr1); }
    }

    // ---- zero-fill rows in [N_FRAMES, N_ROWS) ----
    #pragma unroll
    for (int h = 0; h < 2; h++) {
        int f = f0 + h;
        if (f >= N_FRAMES && f < N_ROWS) {
            float* zm = out + (size_t)f * HALF;
            float* zp = out + (size_t)N_ROWS * HALF + (size_t)f * HALF;
            for (int k = tl; k < HALF; k += 64) { zm[k] = 0.0f; zp[k] = 0.0f; }
        }
    }
}

extern "C" void kernel_launch(void* const* d_in, const int* in_sizes, int n_in,
                              void* d_out, int out_size) {
    const float* x = (const float*)d_in[0];
    float* out = (float*)d_out;
    stft_kernel<<<(N_ROWS + 3) / 4, 128>>>(x, out);
}

// round 8
// speedup vs baseline: 2.2219x; 1.1304x over previous
#include <cuda_runtime.h>

#define SIG_LEN  16777216
#define HOP      256
#define PAD      768
#define N_FRAMES 65539
#define N_ROWS   65542
#define HALF     513

// ---------------- compile-time tables (correctly-rounded, double precision) ----------------
constexpr double PI_D = 3.141592653589793238462643383279502884;

constexpr double tcos(double x) {
    double x2 = x * x, term = 1.0, s = 1.0;
    for (int i = 1; i <= 10; i++) { term *= -x2 / ((2.0 * i - 1.0) * (2.0 * i)); s += term; }
    return s;
}
constexpr double tsin(double x) {
    double x2 = x * x, term = x, s = x;
    for (int i = 1; i <= 10; i++) { term *= -x2 / ((2.0 * i) * (2.0 * i + 1.0)); s += term; }
    return s;
}
constexpr double cpi(double t) {
    while (t >= 2.0) t -= 2.0;
    while (t < 0.0) t += 2.0;
    if (t > 1.0) t = 2.0 - t;
    double sg = 1.0;
    if (t > 0.5) { t = 1.0 - t; sg = -1.0; }
    return sg * (t <= 0.25 ? tcos(PI_D * t) : tsin(PI_D * (0.5 - t)));
}
constexpr double spi(double t) {
    while (t >= 2.0) t -= 2.0;
    while (t < 0.0) t += 2.0;
    double sg = 1.0;
    if (t > 1.0) { t -= 1.0; sg = -1.0; }
    if (t > 0.5) t = 1.0 - t;
    return sg * (t <= 0.25 ? tsin(PI_D * t) : tcos(PI_D * (0.5 - t)));
}

struct Tables {
    float2 tw512[512];     // e^{-2pi i k/512}
    float4 tw64d[64];      // {c,c,s,s} for e^{-2pi i n0 j2/64}
    float4 tw1024d[513];   // {c,c,s,s} for e^{-i pi k/512}
    float2 win[512];       // (w[2n], w[2n+1]) / 32
};
constexpr Tables mk_tables() {
    Tables T{};
    for (int k = 0; k < 512; k++)
        T.tw512[k] = float2{ (float)cpi(k / 256.0), (float)(-spi(k / 256.0)) };
    for (int j2 = 0; j2 < 8; j2++)
        for (int n0 = 0; n0 < 8; n0++) {
            float c = (float)cpi(n0 * j2 / 32.0), s = (float)(-spi(n0 * j2 / 32.0));
            T.tw64d[j2 * 8 + n0] = float4{ c, c, s, s };
        }
    for (int k = 0; k <= 512; k++) {
        float c = (float)cpi(k / 512.0), s = (float)(-spi(k / 512.0));
        T.tw1024d[k] = float4{ c, c, s, s };
    }
    for (int n = 0; n < 512; n++)
        T.win[n] = float2{ (float)((0.54 - 0.46 * cpi(2.0 * (2 * n) / 1023.0)) / 32.0),
                           (float)((0.54 - 0.46 * cpi(2.0 * (2 * n + 1) / 1023.0)) / 32.0) };
    return T;
}
__device__ constexpr Tables TAB = mk_tables();

// ---------------- f32x2 packed primitives (2 frames in the 2 lanes) ----------------
typedef unsigned long long u64;

__device__ __forceinline__ u64 pk(float lo, float hi) {
    u64 r; asm("mov.b64 %0, {%1, %2};" : "=l"(r) : "f"(lo), "f"(hi)); return r;
}
__device__ __forceinline__ void upk(float& lo, float& hi, u64 v) {
    asm("mov.b64 {%0, %1}, %2;" : "=f"(lo), "=f"(hi) : "l"(v));
}
__device__ __forceinline__ u64 vadd(u64 a, u64 b) {
    u64 r; asm("add.rn.f32x2 %0, %1, %2;" : "=l"(r) : "l"(a), "l"(b)); return r;
}
__device__ __forceinline__ u64 vmul(u64 a, u64 b) {
    u64 r; asm("mul.rn.f32x2 %0, %1, %2;" : "=l"(r) : "l"(a), "l"(b)); return r;
}
__device__ __forceinline__ u64 vfma(u64 a, u64 b, u64 c) {
    u64 r; asm("fma.rn.f32x2 %0, %1, %2, %3;" : "=l"(r) : "l"(a), "l"(b), "l"(c)); return r;
}
__device__ __forceinline__ u64 vneg1() { return pk(-1.0f, -1.0f); }
__device__ __forceinline__ u64 vsub(u64 a, u64 b) { return vfma(b, vneg1(), a); }  // exact a-b

struct cp { u64 re, im; };
__device__ __forceinline__ cp cadd(cp a, cp b)   { return { vadd(a.re, b.re), vadd(a.im, b.im) }; }
__device__ __forceinline__ cp csub(cp a, cp b)   { return { vsub(a.re, b.re), vsub(a.im, b.im) }; }
// a + (-i)b = (are+bim, aim-bre);  a - (-i)b = (are-bim, aim+bre)
__device__ __forceinline__ cp caddmi(cp a, cp b) { return { vadd(a.re, b.im), vsub(a.im, b.re) }; }
__device__ __forceinline__ cp csubmi(cp a, cp b) { return { vsub(a.re, b.im), vadd(a.im, b.re) }; }
__device__ __forceinline__ cp cpmul(cp a, cp b) {
    cp r;
    r.re = vsub(vmul(a.re, b.re), vmul(a.im, b.im));
    r.im = vfma(a.re, b.im, vmul(a.im, b.re));
    return r;
}

__device__ __forceinline__ float fsqrt_fast(float x) {
    float r; asm("sqrt.approx.f32 %0, %1;" : "=f"(r) : "f"(x)); return r;
}

// atan2, cephes-style, abs err ~2e-7 rad. (y<0) sign rule maps -0.0 -> +pi (Nyquist).
__device__ __forceinline__ float fatan2_fast(float y, float x) {
    const float PI   = 3.14159265358979323f;
    const float PI_2 = 1.57079632679489662f;
    const float PI_4 = 0.78539816339744831f;
    float ax = fabsf(x), ay = fabsf(y);
    float mn = fminf(ax, ay), mx = fmaxf(ax, ay);
    bool big = mn > 0.41421356f * mx;
    float num = big ? (mn - mx) : mn;
    float den = big ? (mn + mx) : mx;
    float t = __fdividef(num, den);
    t = (den == 0.0f) ? 0.0f : t;
    float s = t * t;
    float p = fmaf(fmaf(fmaf(8.05374449538e-2f, s, -1.38776856032e-1f), s,
                        1.99777106478e-1f), s, -3.33329491539e-1f);
    float r = fmaf(p * s, t, t);
    if (big) r += PI_4;
    if (ay > ax) r = PI_2 - r;
    if (x < 0.0f) r = PI - r;
    return (y < 0.0f) ? -r : r;
}

// packed 8-point DFT (both frames simultaneously)
__device__ __forceinline__ void fft8p(cp* a) {
    const float Cf = 0.70710678118654752440f;
    u64 Cd = pk(Cf, Cf), nCd = pk(-Cf, -Cf);
    cp s0 = cadd(a[0], a[4]), s1 = csub(a[0], a[4]);
    cp s2 = cadd(a[2], a[6]), s3 = csub(a[2], a[6]);
    cp t0 = cadd(a[1], a[5]), t1 = csub(a[1], a[5]);
    cp t2 = cadd(a[3], a[7]), t3 = csub(a[3], a[7]);
    cp E0 = cadd(s0, s2), E2 = csub(s0, s2);
    cp E1 = caddmi(s1, s3), E3 = csubmi(s1, s3);
    cp O0 = cadd(t0, t2), O2 = csub(t0, t2);
    cp O1 = caddmi(t1, t3), O3 = csubmi(t1, t3);
    cp W1 = { vmul(vadd(O1.re, O1.im), Cd), vmul(vsub(O1.im, O1.re), Cd) };
    cp W3 = { vmul(vsub(O3.im, O3.re), Cd), vmul(vadd(O3.re, O3.im), nCd) };
    a[0] = cadd(E0, O0);   a[4] = csub(E0, O0);
    a[1] = cadd(E1, W1);   a[5] = csub(E1, W1);
    a[2] = caddmi(E2, O2); a[6] = csubmi(E2, O2);   // W2 = -i*O2 folded
    a[3] = cadd(E3, W3);   a[7] = csub(E3, W3);
}

// ---------------- fused STFT kernel: 128 threads, 2 frame-pairs (4 frames)/block ----------
// Single shared buffer (read-all-to-regs, sync, overwrite) -> 16KB/block, 8 blocks/SM.
__global__ __launch_bounds__(128, 8) void stft_kernel(const float* __restrict__ x,
                                                      float* __restrict__ out) {
    __shared__ ulonglong2 sA[2][512];

    const int t  = threadIdx.x;
    const int pr = t >> 6;            // frame-pair slot (0-1)
    const int tl = t & 63;
    const int f0 = blockIdx.x * 4 + pr * 2;   // lane .x frame
    const int f1 = f0 + 1;                    // lane .y frame
    const int st0 = f0 * HOP - PAD;
    const int st1 = st0 + HOP;
    const int hi = tl >> 3, lo = tl & 7;

    cp v[8];

    // ---- load + window (both frames) ----
    const bool inb0 = (st0 >= 0) && (st0 + 1024 <= SIG_LEN);
    const bool inb1 = (st1 >= 0) && (st1 + 1024 <= SIG_LEN);
    #pragma unroll
    for (int m = 0; m < 8; m++) {
        int n = tl + 64 * m;
        float2 w = TAB.win[n];
        float a0, b0, a1, b1;
        if (inb0) { float2 xv = *(const float2*)(x + st0 + 2 * n); a0 = xv.x; b0 = xv.y; }
        else {
            int i0 = st0 + 2 * n;
            a0 = (i0     >= 0 && i0     < SIG_LEN) ? x[i0]     : 0.0f;
            b0 = (i0 + 1 >= 0 && i0 + 1 < SIG_LEN) ? x[i0 + 1] : 0.0f;
        }
        if (inb1) { float2 xv = *(const float2*)(x + st1 + 2 * n); a1 = xv.x; b1 = xv.y; }
        else {
            int i1 = st1 + 2 * n;
            a1 = (i1     >= 0 && i1     < SIG_LEN) ? x[i1]     : 0.0f;
            b1 = (i1 + 1 >= 0 && i1 + 1 < SIG_LEN) ? x[i1 + 1] : 0.0f;
        }
        v[m].re = vmul(pk(a0, a1), pk(w.x, w.x));
        v[m].im = vmul(pk(b0, b1), pk(w.y, w.y));
    }

    // ---- stage 1: fft8 + twiddle powers of tw512[tl] (interleaved: only w1..w4 live) ----
    fft8p(v);
    {
        float2 w1s = TAB.tw512[tl];
        cp w1 = { pk(w1s.x, w1s.x), pk(w1s.y, w1s.y) };
        v[1] = cpmul(v[1], w1);
        cp w2 = cpmul(w1, w1);
        v[2] = cpmul(v[2], w2);
        cp w3 = cpmul(w2, w1);
        v[3] = cpmul(v[3], w3);
        cp w4 = cpmul(w2, w2);
        v[4] = cpmul(v[4], w4);
        v[5] = cpmul(v[5], cpmul(w4, w1));
        v[6] = cpmul(v[6], cpmul(w3, w3));
        v[7] = cpmul(v[7], cpmul(w4, w3));
    }
    ulonglong2* bufA = sA[pr];
    #pragma unroll
    for (int j = 0; j < 8; j++)
        bufA[j * 64 + (((hi ^ j) & 7) << 3) + lo] = make_ulonglong2(v[j].re, v[j].im);
    __syncthreads();

    // ---- stage 2 (read all -> sync -> overwrite same buffer) ----
    #pragma unroll
    for (int m = 0; m < 8; m++) {
        ulonglong2 e = bufA[hi * 64 + (((m ^ hi) & 7) << 3) + lo];
        v[m].re = e.x; v[m].im = e.y;
    }
    fft8p(v);
    #pragma unroll
    for (int j2 = 1; j2 < 8; j2++) {
        float4 wd = TAB.tw64d[j2 * 8 + lo];
        cp w = { pk(wd.x, wd.y), pk(wd.z, wd.w) };
        v[j2] = cpmul(v[j2], w);
    }
    __syncthreads();
    #pragma unroll
    for (int j2 = 0; j2 < 8; j2++)
        bufA[j2 * 64 + hi * 8 + (lo ^ j2)] = make_ulonglong2(v[j2].re, v[j2].im);
    __syncthreads();

    // ---- stage 3 ----
    #pragma unroll
    for (int n0 = 0; n0 < 8; n0++) {
        ulonglong2 e = bufA[lo * 64 + hi * 8 + (n0 ^ lo)];
        v[n0].re = e.x; v[n0].im = e.y;
    }
    fft8p(v);
    __syncthreads();
    #pragma unroll
    for (int j3 = 0; j3 < 8; j3++) {
        int k = hi + 8 * lo + 64 * j3;
        bufA[k ^ lo] = make_ulonglong2(v[j3].re, v[j3].im);   // addrR(k)=k^((k>>3)&7)
    }
    __syncthreads();

    // ---- conjugate-pair untangle (packed) + (-1)^k shift + mag/phase (scalar/frame) ----
    float* om0 = out + (size_t)f0 * HALF;
    float* op0 = out + (size_t)N_ROWS * HALF + (size_t)f0 * HALF;
    float* om1 = om0 + HALF;
    float* op1 = op0 + HALF;
    const bool w0 = (f0 < N_FRAMES);
    const bool w1 = (f1 < N_FRAMES);
    const u64 Hd = pk(0.5f, 0.5f);

    const float sg = (tl & 1) ? -1.0f : 1.0f;
    const float ng = -sg;
    #pragma unroll
    for (int q = 0; q < 4; q++) {
        int k  = tl + 64 * q;                  // 0..255
        int ka = k & 511, kb = (512 - k) & 511;
        ulonglong2 ek = bufA[ka ^ ((ka >> 3) & 7)];
        ulonglong2 em = bufA[kb ^ ((kb >> 3) & 7)];
        cp zk = { ek.x, ek.y }, zm = { em.x, em.y };
        u64 Ar = vmul(vadd(zk.re, zm.re), Hd);
        u64 Ai = vmul(vsub(zk.im, zm.im), Hd);
        u64 Br = vmul(vsub(zk.re, zm.re), Hd);
        u64 Bi = vmul(vadd(zk.im, zm.im), Hd);
        float4 wd = TAB.tw1024d[k];
        u64 wc = pk(wd.x, wd.y), ws = pk(wd.z, wd.w);
        u64 wbr = vsub(vmul(wc, Br), vmul(ws, Bi));
        u64 wbi = vfma(wc, Bi, vmul(ws, Br));
        u64 Xkr = vadd(Ar, wbi), Xki = vsub(Ai, wbr);
        u64 Xmr = vsub(Ar, wbi), nXmi = vadd(Ai, wbr);   // Xmi = -nXmi (sign folded below)
        u64 Mk = vfma(Xki, Xki, vmul(Xkr, Xkr));
        u64 Mm = vfma(nXmi, nXmi, vmul(Xmr, Xmr));
        float mk0, mk1, mm0, mm1, kr0, kr1, ki0, ki1, mr0, mr1, ni0, ni1;
        upk(mk0, mk1, Mk); upk(mm0, mm1, Mm);
        upk(kr0, kr1, Xkr); upk(ki0, ki1, Xki);
        upk(mr0, mr1, Xmr); upk(ni0, ni1, nXmi);
        int m = 512 - k;
        if (w0) {
            om0[k] = fsqrt_fast(mk0); op0[k] = fatan2_fast(sg * ki0, sg * kr0);
            om0[m] = fsqrt_fast(mm0); op0[m] = fatan2_fast(ng * ni0, sg * mr0);
        }
        if (w1) {
            om1[k] = fsqrt_fast(mk1); op1[k] = fatan2_fast(sg * ki1, sg * kr1);
            om1[m] = fsqrt_fast(mm1); op1[m] = fatan2_fast(ng * ni1, sg * mr1);
        }
    }
    if (tl == 0) {                      // center bin k=256: X = conj(Z256), even parity
        ulonglong2 e = bufA[256];       // 256 ^ ((256>>3)&7) == 256
        float zr0, zr1, zi0, zi1;
        upk(zr0, zr1, e.x); upk(zi0, zi1, e.y);
        if (w0) { om0[256] = fsqrt_fast(zr0 * zr0 + zi0 * zi0); op0[256] = fatan2_fast(-zi0, zr0); }
        if (w1) { om1[256] = fsqrt_fast(zr1 * zr1 + zi1 * zi1); op1[256] = fatan2_fast(-zi1, zr1); }
    }

    // ---- zero-fill rows in [N_FRAMES, N_ROWS) ----
    #pragma unroll
    for (int h = 0; h < 2; h++) {
        int f = f0 + h;
        if (f >= N_FRAMES && f < N_ROWS) {
            float* zm = out + (size_t)f * HALF;
            float* zp = out + (size_t)N_ROWS * HALF + (size_t)f * HALF;
            for (int k = tl; k < HALF; k += 64) { zm[k] = 0.0f; zp[k] = 0.0f; }
        }
    }
}

extern "C" void kernel_launch(void* const* d_in, const int* in_sizes, int n_in,
                              void* d_out, int out_size) {
    const float* x = (const float*)d_in[0];
    float* out = (float*)d_out;
    stft_kernel<<<(N_ROWS + 3) / 4, 128>>>(x, out);
}

// round 9
// speedup vs baseline: 2.5850x; 1.1634x over previous
#include <cuda_runtime.h>

#define SIG_LEN  16777216
#define HOP      256
#define PAD      768
#define N_FRAMES 65539
#define N_ROWS   65542
#define HALF     513

// ---------------- compile-time tables (correctly-rounded, double precision) ----------------
constexpr double PI_D = 3.141592653589793238462643383279502884;

constexpr double tcos(double x) {
    double x2 = x * x, term = 1.0, s = 1.0;
    for (int i = 1; i <= 10; i++) { term *= -x2 / ((2.0 * i - 1.0) * (2.0 * i)); s += term; }
    return s;
}
constexpr double tsin(double x) {
    double x2 = x * x, term = x, s = x;
    for (int i = 1; i <= 10; i++) { term *= -x2 / ((2.0 * i) * (2.0 * i + 1.0)); s += term; }
    return s;
}
constexpr double cpi(double t) {
    while (t >= 2.0) t -= 2.0;
    while (t < 0.0) t += 2.0;
    if (t > 1.0) t = 2.0 - t;
    double sg = 1.0;
    if (t > 0.5) { t = 1.0 - t; sg = -1.0; }
    return sg * (t <= 0.25 ? tcos(PI_D * t) : tsin(PI_D * (0.5 - t)));
}
constexpr double spi(double t) {
    while (t >= 2.0) t -= 2.0;
    while (t < 0.0) t += 2.0;
    double sg = 1.0;
    if (t > 1.0) { t -= 1.0; sg = -1.0; }
    if (t > 0.5) t = 1.0 - t;
    return sg * (t <= 0.25 ? tsin(PI_D * t) : tcos(PI_D * (0.5 - t)));
}

struct Tables {
    float2 tw512[512];     // e^{-2pi i k/512}
    float4 tw64d[64];      // {c,c,s,s} for e^{-2pi i n0 j2/64}
    float4 tw1024d[513];   // {c,c,s,s} for e^{-i pi k/512}
    float2 win[512];       // (w[2n], w[2n+1]) / 32
};
constexpr Tables mk_tables() {
    Tables T{};
    for (int k = 0; k < 512; k++)
        T.tw512[k] = float2{ (float)cpi(k / 256.0), (float)(-spi(k / 256.0)) };
    for (int j2 = 0; j2 < 8; j2++)
        for (int n0 = 0; n0 < 8; n0++) {
            float c = (float)cpi(n0 * j2 / 32.0), s = (float)(-spi(n0 * j2 / 32.0));
            T.tw64d[j2 * 8 + n0] = float4{ c, c, s, s };
        }
    for (int k = 0; k <= 512; k++) {
        float c = (float)cpi(k / 512.0), s = (float)(-spi(k / 512.0));
        T.tw1024d[k] = float4{ c, c, s, s };
    }
    for (int n = 0; n < 512; n++)
        T.win[n] = float2{ (float)((0.54 - 0.46 * cpi(2.0 * (2 * n) / 1023.0)) / 32.0),
                           (float)((0.54 - 0.46 * cpi(2.0 * (2 * n + 1) / 1023.0)) / 32.0) };
    return T;
}
__device__ constexpr Tables TAB = mk_tables();

// ---------------- f32x2 packed primitives (2 frames in the 2 lanes) ----------------
typedef unsigned long long u64;

__device__ __forceinline__ u64 pk(float lo, float hi) {
    u64 r; asm("mov.b64 %0, {%1, %2};" : "=l"(r) : "f"(lo), "f"(hi)); return r;
}
__device__ __forceinline__ void upk(float& lo, float& hi, u64 v) {
    asm("mov.b64 {%0, %1}, %2;" : "=f"(lo), "=f"(hi) : "l"(v));
}
__device__ __forceinline__ u64 vadd(u64 a, u64 b) {
    u64 r; asm("add.rn.f32x2 %0, %1, %2;" : "=l"(r) : "l"(a), "l"(b)); return r;
}
__device__ __forceinline__ u64 vmul(u64 a, u64 b) {
    u64 r; asm("mul.rn.f32x2 %0, %1, %2;" : "=l"(r) : "l"(a), "l"(b)); return r;
}
__device__ __forceinline__ u64 vfma(u64 a, u64 b, u64 c) {
    u64 r; asm("fma.rn.f32x2 %0, %1, %2, %3;" : "=l"(r) : "l"(a), "l"(b), "l"(c)); return r;
}
__device__ __forceinline__ u64 vneg1() { return pk(-1.0f, -1.0f); }
__device__ __forceinline__ u64 vsub(u64 a, u64 b) { return vfma(b, vneg1(), a); }  // exact a-b

struct cp { u64 re, im; };
__device__ __forceinline__ cp cadd(cp a, cp b)   { return { vadd(a.re, b.re), vadd(a.im, b.im) }; }
__device__ __forceinline__ cp csub(cp a, cp b)   { return { vsub(a.re, b.re), vsub(a.im, b.im) }; }
// a + (-i)b = (are+bim, aim-bre);  a - (-i)b = (are-bim, aim+bre)
__device__ __forceinline__ cp caddmi(cp a, cp b) { return { vadd(a.re, b.im), vsub(a.im, b.re) }; }
__device__ __forceinline__ cp csubmi(cp a, cp b) { return { vsub(a.re, b.im), vadd(a.im, b.re) }; }
__device__ __forceinline__ cp cpmul(cp a, cp b) {
    cp r;
    r.re = vsub(vmul(a.re, b.re), vmul(a.im, b.im));
    r.im = vfma(a.re, b.im, vmul(a.im, b.re));
    return r;
}

__device__ __forceinline__ float fsqrt_fast(float x) {
    float r; asm("sqrt.approx.f32 %0, %1;" : "=f"(r) : "f"(x)); return r;
}

// Half-angle atan2 reusing r = sqrt(x^2+y^2) (already computed for magnitude).
//   x >= 0: theta = 2*atan(y/(r+|x|))           (argument always in [-1,1])
//   x <  0: theta = sign(y)*pi - 2*atan(y/(r+|x|))
// 6-coeff odd minimax for atan on [-1,1] (abs err ~1e-5 rad), x2 folded into coeffs.
// Sign via (y<0) comparison: y==-0.0 & x<0 -> +pi, matching reference at the
// Nyquist bin (our pair formula makes Im = -0.0 there; rfft reference has +0).
__device__ __forceinline__ float fatan2_half(float y, float x, float r) {
    const float PI = 3.14159265358979323f;
    float den = r + fabsf(x);
    float t = __fdividef(y, den);
    t = (den == 0.0f) ? 0.0f : t;          // atan2(0,0) = 0
    float s = t * t;
    float p = fmaf(fmaf(fmaf(fmaf(fmaf(-0.02344240f, s, 0.10530664f), s,
                 -0.23286574f), s, 0.38708692f), s, -0.66524694f), s, 1.99995452f);
    float th = t * p;                       // 2*atan(t)
    if (x < 0.0f) th = ((y < 0.0f) ? -PI : PI) - th;
    return th;
}

// packed 8-point DFT (both frames simultaneously)
__device__ __forceinline__ void fft8p(cp* a) {
    const float Cf = 0.70710678118654752440f;
    u64 Cd = pk(Cf, Cf), nCd = pk(-Cf, -Cf);
    cp s0 = cadd(a[0], a[4]), s1 = csub(a[0], a[4]);
    cp s2 = cadd(a[2], a[6]), s3 = csub(a[2], a[6]);
    cp t0 = cadd(a[1], a[5]), t1 = csub(a[1], a[5]);
    cp t2 = cadd(a[3], a[7]), t3 = csub(a[3], a[7]);
    cp E0 = cadd(s0, s2), E2 = csub(s0, s2);
    cp E1 = caddmi(s1, s3), E3 = csubmi(s1, s3);
    cp O0 = cadd(t0, t2), O2 = csub(t0, t2);
    cp O1 = caddmi(t1, t3), O3 = csubmi(t1, t3);
    cp W1 = { vmul(vadd(O1.re, O1.im), Cd), vmul(vsub(O1.im, O1.re), Cd) };
    cp W3 = { vmul(vsub(O3.im, O3.re), Cd), vmul(vadd(O3.re, O3.im), nCd) };
    a[0] = cadd(E0, O0);   a[4] = csub(E0, O0);
    a[1] = cadd(E1, W1);   a[5] = csub(E1, W1);
    a[2] = caddmi(E2, O2); a[6] = csubmi(E2, O2);   // W2 = -i*O2 folded
    a[3] = cadd(E3, W3);   a[7] = csub(E3, W3);
}

// ---------------- fused STFT kernel: 128 threads, 2 frame-pairs (4 frames)/block ----------
__global__ __launch_bounds__(128, 8) void stft_kernel(const float* __restrict__ x,
                                                      float* __restrict__ out) {
    __shared__ ulonglong2 sA[2][512];

    const int t  = threadIdx.x;
    const int pr = t >> 6;            // frame-pair slot (0-1)
    const int tl = t & 63;
    const int f0 = blockIdx.x * 4 + pr * 2;   // lane .x frame
    const int f1 = f0 + 1;                    // lane .y frame
    const int st0 = f0 * HOP - PAD;
    const int hi = tl >> 3, lo = tl & 7;

    cp v[8];

    // ---- load (shared across lanes: frame1 sample n == frame0 sample n+128,
    //      i.e. m+2 in this loop) + window ----
    float2 xs[10];
    const bool inb = (st0 >= 0) && (st0 + 2 * (tl + 64 * 9) + 2 <= SIG_LEN);
    if (inb) {
        #pragma unroll
        for (int m = 0; m < 10; m++)
            xs[m] = *(const float2*)(x + st0 + 2 * (tl + 64 * m));
    } else {
        #pragma unroll
        for (int m = 0; m < 10; m++) {
            int i0 = st0 + 2 * (tl + 64 * m);
            xs[m].x = (i0     >= 0 && i0     < SIG_LEN) ? x[i0]     : 0.0f;
            xs[m].y = (i0 + 1 >= 0 && i0 + 1 < SIG_LEN) ? x[i0 + 1] : 0.0f;
        }
    }
    #pragma unroll
    for (int m = 0; m < 8; m++) {
        float2 w = TAB.win[tl + 64 * m];
        v[m].re = vmul(pk(xs[m].x, xs[m + 2].x), pk(w.x, w.x));
        v[m].im = vmul(pk(xs[m].y, xs[m + 2].y), pk(w.y, w.y));
    }

    // ---- stage 1: fft8 + twiddle powers of tw512[tl] (interleaved: only w1..w4 live) ----
    fft8p(v);
    {
        float2 w1s = TAB.tw512[tl];
        cp w1 = { pk(w1s.x, w1s.x), pk(w1s.y, w1s.y) };
        v[1] = cpmul(v[1], w1);
        cp w2 = cpmul(w1, w1);
        v[2] = cpmul(v[2], w2);
        cp w3 = cpmul(w2, w1);
        v[3] = cpmul(v[3], w3);
        cp w4 = cpmul(w2, w2);
        v[4] = cpmul(v[4], w4);
        v[5] = cpmul(v[5], cpmul(w4, w1));
        v[6] = cpmul(v[6], cpmul(w3, w3));
        v[7] = cpmul(v[7], cpmul(w4, w3));
    }
    ulonglong2* bufA = sA[pr];
    #pragma unroll
    for (int j = 0; j < 8; j++)
        bufA[j * 64 + (((hi ^ j) & 7) << 3) + lo] = make_ulonglong2(v[j].re, v[j].im);
    __syncthreads();

    // ---- stage 2 (read all -> sync -> overwrite same buffer) ----
    #pragma unroll
    for (int m = 0; m < 8; m++) {
        ulonglong2 e = bufA[hi * 64 + (((m ^ hi) & 7) << 3) + lo];
        v[m].re = e.x; v[m].im = e.y;
    }
    fft8p(v);
    #pragma unroll
    for (int j2 = 1; j2 < 8; j2++) {
        float4 wd = TAB.tw64d[j2 * 8 + lo];
        cp w = { pk(wd.x, wd.y), pk(wd.z, wd.w) };
        v[j2] = cpmul(v[j2], w);
    }
    __syncthreads();
    #pragma unroll
    for (int j2 = 0; j2 < 8; j2++)
        bufA[j2 * 64 + hi * 8 + (lo ^ j2)] = make_ulonglong2(v[j2].re, v[j2].im);
    __syncthreads();

    // ---- stage 3 ----
    #pragma unroll
    for (int n0 = 0; n0 < 8; n0++) {
        ulonglong2 e = bufA[lo * 64 + hi * 8 + (n0 ^ lo)];
        v[n0].re = e.x; v[n0].im = e.y;
    }
    fft8p(v);
    __syncthreads();
    #pragma unroll
    for (int j3 = 0; j3 < 8; j3++) {
        int k = hi + 8 * lo + 64 * j3;
        bufA[k ^ lo] = make_ulonglong2(v[j3].re, v[j3].im);   // addrR(k)=k^((k>>3)&7)
    }
    __syncthreads();

    // ---- conjugate-pair untangle (packed) + (-1)^k shift + mag/phase (scalar/frame) ----
    float* om0 = out + (size_t)f0 * HALF;
    float* op0 = out + (size_t)N_ROWS * HALF + (size_t)f0 * HALF;
    float* om1 = om0 + HALF;
    float* op1 = op0 + HALF;
    const bool w0 = (f0 < N_FRAMES);
    const bool w1 = (f1 < N_FRAMES);
    const u64 Hd = pk(0.5f, 0.5f);

    const float sg = (tl & 1) ? -1.0f : 1.0f;
    const float ng = -sg;
    #pragma unroll
    for (int q = 0; q < 4; q++) {
        int k  = tl + 64 * q;                  // 0..255
        int ka = k & 511, kb = (512 - k) & 511;
        ulonglong2 ek = bufA[ka ^ ((ka >> 3) & 7)];
        ulonglong2 em = bufA[kb ^ ((kb >> 3) & 7)];
        cp zk = { ek.x, ek.y }, zm = { em.x, em.y };
        u64 Ar = vmul(vadd(zk.re, zm.re), Hd);
        u64 Ai = vmul(vsub(zk.im, zm.im), Hd);
        u64 Br = vmul(vsub(zk.re, zm.re), Hd);
        u64 Bi = vmul(vadd(zk.im, zm.im), Hd);
        float4 wd = TAB.tw1024d[k];
        u64 wc = pk(wd.x, wd.y), ws = pk(wd.z, wd.w);
        u64 wbr = vsub(vmul(wc, Br), vmul(ws, Bi));
        u64 wbi = vfma(wc, Bi, vmul(ws, Br));
        u64 Xkr = vadd(Ar, wbi), Xki = vsub(Ai, wbr);
        u64 Xmr = vsub(Ar, wbi), nXmi = vadd(Ai, wbr);   // Xmi = -nXmi (sign folded below)
        u64 Mk = vfma(Xki, Xki, vmul(Xkr, Xkr));
        u64 Mm = vfma(nXmi, nXmi, vmul(Xmr, Xmr));
        float mk0, mk1, mm0, mm1, kr0, kr1, ki0, ki1, mr0, mr1, ni0, ni1;
        upk(mk0, mk1, Mk); upk(mm0, mm1, Mm);
        upk(kr0, kr1, Xkr); upk(ki0, ki1, Xki);
        upk(mr0, mr1, Xmr); upk(ni0, ni1, nXmi);
        int m = 512 - k;
        if (w0) {
            float rk = fsqrt_fast(mk0), rm = fsqrt_fast(mm0);
            om0[k] = rk; op0[k] = fatan2_half(sg * ki0, sg * kr0, rk);
            om0[m] = rm; op0[m] = fatan2_half(ng * ni0, sg * mr0, rm);
        }
        if (w1) {
            float rk = fsqrt_fast(mk1), rm = fsqrt_fast(mm1);
            om1[k] = rk; op1[k] = fatan2_half(sg * ki1, sg * kr1, rk);
            om1[m] = rm; op1[m] = fatan2_half(ng * ni1, sg * mr1, rm);
        }
    }
    if (tl == 0) {                      // center bin k=256: X = conj(Z256), even parity
        ulonglong2 e = bufA[256];       // 256 ^ ((256>>3)&7) == 256
        float zr0, zr1, zi0, zi1;
        upk(zr0, zr1, e.x); upk(zi0, zi1, e.y);
        if (w0) {
            float r = fsqrt_fast(zr0 * zr0 + zi0 * zi0);
            om0[256] = r; op0[256] = fatan2_half(-zi0, zr0, r);
        }
        if (w1) {
            float r = fsqrt_fast(zr1 * zr1 + zi1 * zi1);
            om1[256] = r; op1[256] = fatan2_half(-zi1, zr1, r);
        }
    }

    // ---- zero-fill rows in [N_FRAMES, N_ROWS) ----
    #pragma unroll
    for (int h = 0; h < 2; h++) {
        int f = f0 + h;
        if (f >= N_FRAMES && f < N_ROWS) {
            float* zm = out + (size_t)f * HALF;
            float* zp = out + (size_t)N_ROWS * HALF + (size_t)f * HALF;
            for (int k = tl; k < HALF; k += 64) { zm[k] = 0.0f; zp[k] = 0.0f; }
        }
    }
}

extern "C" void kernel_launch(void* const* d_in, const int* in_sizes, int n_in,
                              void* d_out, int out_size) {
    const float* x = (const float*)d_in[0];
    float* out = (float*)d_out;
    stft_kernel<<<(N_ROWS + 3) / 4, 128>>>(x, out);
}